// round 2
// baseline (speedup 1.0000x reference)
#include <cuda_runtime.h>
#include <cstdint>

// Problem constants
#define B_SZ 256
#define W_SZ 4096
#define L_SZ 16
#define K_SZ 8

// Ping-pong activation scratch in transposed layout: h_t[n][b]  (n-major, b fast)
// 2 * 4096 * 256 * 4B = 8 MB
__device__ float g_h[2][(size_t)W_SZ * B_SZ];

// Detected element width of inv_mask input: 1 (bool/uint8) or 4 (int32/float32).
__device__ int g_inv_width;

// ---------------------------------------------------------------------------
// Kernel 0: detect inv_mask element width.
// For 4-byte encodings of {0,1} (int32 or float32), every byte at offset
// ==1 (mod 4) is zero. For 1-byte bools, those bytes are ~Bernoulli(0.5).
// 256 samples -> false-positive probability 2^-256.
// ---------------------------------------------------------------------------
__global__ void detect_inv_width_kernel(const unsigned char* __restrict__ inv)
{
    if (threadIdx.x == 0 && blockIdx.x == 0) {
        int w = 4;
        for (int i = 1; i < 1024; i += 4) {
            if (inv[i] != 0) { w = 1; break; }
        }
        g_inv_width = w;
    }
}

// ---------------------------------------------------------------------------
// Kernel 1: fused prior + transpose.
//   h_t[n][b] = relu(obs[b][n] * pw[n] + pb[n])
// obs is [B][W] row-major; read coalesced along n, write coalesced along b.
// ---------------------------------------------------------------------------
__global__ void __launch_bounds__(256) prior_transpose_kernel(
    const float* __restrict__ obs,
    const float* __restrict__ pw,
    const float* __restrict__ pb)
{
    __shared__ float tile[32][33];
    const int n0 = blockIdx.x * 32;
    const int b0 = blockIdx.y * 32;
    const int tx = threadIdx.x;   // 0..31
    const int ty = threadIdx.y;   // 0..7

#pragma unroll
    for (int j = 0; j < 4; j++) {
        int b = b0 + ty + j * 8;
        // tile[b_local][n_local]
        tile[ty + j * 8][tx] = obs[(size_t)b * W_SZ + n0 + tx];
    }
    __syncthreads();
#pragma unroll
    for (int j = 0; j < 4; j++) {
        int n = n0 + ty + j * 8;
        int b = b0 + tx;
        float v = tile[tx][ty + j * 8];          // [b_local=tx][n_local=ty+j*8]
        v = fmaxf(fmaf(v, __ldg(pw + n), __ldg(pb + n)), 0.0f);
        g_h[0][(size_t)n * B_SZ + b] = v;
    }
}

// ---------------------------------------------------------------------------
// Kernel 2: one scan level.
//   h_out[n][b] = relu( Σ_k w'[n,k] * h_in[p[n,k]][b] + bias'[n] )
// Warp: 32 lanes share one n (params uniform), each lane owns 4 consecutive b.
// Gathers are fully coalesced float4 loads (512B per warp per k).
// Grid: W * B/4 threads = 262144 -> 1024 blocks of 256.
// ---------------------------------------------------------------------------
__global__ void __launch_bounds__(256) level_kernel(
    int src,
    int lvl,
    const float*         __restrict__ weights,   // [W][K] for this level
    const float*         __restrict__ biases,    // [W]
    const int*           __restrict__ parents,   // [W][K]
    const unsigned char* __restrict__ inv_base)  // [L-1][W], element width in g_inv_width
{
    const float* __restrict__ hin  = g_h[src];
    float*       __restrict__ hout = g_h[src ^ 1];

    const int gid = blockIdx.x * 256 + threadIdx.x;
    const int n   = gid >> 6;          // 64 threads (B/4) per n
    const int b   = (gid & 63) << 2;   // lane's 4-wide batch slice

    // Per-n params (uniform across the 32 lanes of a warp -> single transactions)
    const int4*   pp = reinterpret_cast<const int4*>(parents + (size_t)n * K_SZ);
    const float4* wp = reinterpret_cast<const float4*>(weights + (size_t)n * K_SZ);
    int4   p0 = __ldg(pp);
    int4   p1 = __ldg(pp + 1);
    float4 w0 = __ldg(wp);
    float4 w1 = __ldg(wp + 1);
    float  bb = __ldg(biases + n);

    // inv_mask load with runtime-detected element width.
    // width 4: nonzero 32-bit word == true for both int32 {0,1} and fp32 {0,1.0f}.
    bool iv;
    if (g_inv_width == 4) {
        const unsigned* iw = reinterpret_cast<const unsigned*>(inv_base);
        iv = (__ldg(iw + (size_t)lvl * W_SZ + n) != 0u);
    } else {
        iv = (__ldg(inv_base + (size_t)lvl * W_SZ + n) != 0);
    }

    // Fold inversion:  Σ w*(1-x) + b  ==  Σ (-w)*x + (b + Σw)
    float sw = ((w0.x + w0.y) + (w0.z + w0.w)) + ((w1.x + w1.y) + (w1.z + w1.w));
    float base = iv ? (bb + sw) : bb;
    float sgn  = iv ? -1.0f : 1.0f;
    w0.x *= sgn; w0.y *= sgn; w0.z *= sgn; w0.w *= sgn;
    w1.x *= sgn; w1.y *= sgn; w1.z *= sgn; w1.w *= sgn;

    float4 acc = make_float4(base, base, base, base);

#define GATHER_STEP(P, WV)                                                        \
    {                                                                             \
        float4 x = __ldg(reinterpret_cast<const float4*>(                         \
            hin + (((size_t)(P)) << 8) + b));                                     \
        acc.x = fmaf((WV), x.x, acc.x);                                           \
        acc.y = fmaf((WV), x.y, acc.y);                                           \
        acc.z = fmaf((WV), x.z, acc.z);                                           \
        acc.w = fmaf((WV), x.w, acc.w);                                           \
    }

    GATHER_STEP(p0.x, w0.x)
    GATHER_STEP(p0.y, w0.y)
    GATHER_STEP(p0.z, w0.z)
    GATHER_STEP(p0.w, w0.w)
    GATHER_STEP(p1.x, w1.x)
    GATHER_STEP(p1.y, w1.y)
    GATHER_STEP(p1.z, w1.z)
    GATHER_STEP(p1.w, w1.w)
#undef GATHER_STEP

    acc.x = fmaxf(acc.x, 0.0f);
    acc.y = fmaxf(acc.y, 0.0f);
    acc.z = fmaxf(acc.z, 0.0f);
    acc.w = fmaxf(acc.w, 0.0f);

    *reinterpret_cast<float4*>(hout + (size_t)n * B_SZ + b) = acc;
}

// ---------------------------------------------------------------------------
// Kernel 3: final transpose back to reference layout.
//   out[b][n] = h_t[n][b]   (source buffer index 1 after 15 levels)
// ---------------------------------------------------------------------------
__global__ void __launch_bounds__(256) out_transpose_kernel(float* __restrict__ out)
{
    __shared__ float tile[32][33];
    const int b0 = blockIdx.x * 32;
    const int n0 = blockIdx.y * 32;
    const int tx = threadIdx.x;
    const int ty = threadIdx.y;

#pragma unroll
    for (int j = 0; j < 4; j++) {
        int n = n0 + ty + j * 8;
        // tile[n_local][b_local]
        tile[ty + j * 8][tx] = g_h[1][(size_t)n * B_SZ + b0 + tx];
    }
    __syncthreads();
#pragma unroll
    for (int j = 0; j < 4; j++) {
        int b = b0 + ty + j * 8;
        out[(size_t)b * W_SZ + n0 + tx] = tile[tx][ty + j * 8];
    }
}

// ---------------------------------------------------------------------------
// Launch
// ---------------------------------------------------------------------------
extern "C" void kernel_launch(void* const* d_in, const int* in_sizes, int n_in,
                              void* d_out, int out_size)
{
    const float*         obs     = (const float*)d_in[0];         // [B, W]
    const float*         pw      = (const float*)d_in[1];         // [W]
    const float*         pb      = (const float*)d_in[2];         // [W]
    const float*         weights = (const float*)d_in[3];         // [L-1, W, K]
    const float*         biases  = (const float*)d_in[4];         // [L-1, W]
    const int*           parents = (const int*)d_in[5];           // [L-1, W, K]
    const unsigned char* inv     = (const unsigned char*)d_in[6]; // [L-1, W] bool (width TBD)
    float*               out     = (float*)d_out;                 // [B, W]

    (void)in_sizes; (void)n_in; (void)out_size;

    // Detect inv_mask element width (1 vs 4 bytes)
    detect_inv_width_kernel<<<1, 32>>>(inv);

    // Prior + transpose into g_h[0]
    prior_transpose_kernel<<<dim3(W_SZ / 32, B_SZ / 32), dim3(32, 8)>>>(obs, pw, pb);

    // 15 scan levels, ping-pong g_h[0] <-> g_h[1]
    const int blocks = (W_SZ * (B_SZ / 4)) / 256;  // 1024
    for (int l = 0; l < L_SZ - 1; l++) {
        level_kernel<<<blocks, 256>>>(
            l & 1, l,
            weights + (size_t)l * W_SZ * K_SZ,
            biases  + (size_t)l * W_SZ,
            parents + (size_t)l * W_SZ * K_SZ,
            inv);
    }

    // After 15 levels (last l=14, even -> wrote g_h[1]), transpose to output
    out_transpose_kernel<<<dim3(B_SZ / 32, W_SZ / 32), dim3(32, 8)>>>(out);
}